// round 5
// baseline (speedup 1.0000x reference)
#include <cuda_runtime.h>
#include <math.h>

// Problem constants (fixed by setup_inputs)
#define NB 16
#define NP 32768
#define NG 128
#define TG 4            // truths per block
#define TK 4            // top-k (expand_num)
#define PSPLIT 8        // prior-dimension split
#define PCHUNK (NP / PSPLIT)        // 4096 priors per block
#define NT1 128
#define NWARPS1 (NT1 / 32)
#define NBG (NB * NG)               // 2048 (b,g) pairs
#define NLISTS (PSPLIT * NWARPS1)   // 32 partial lists per (b,g)
#define NCAND (NLISTS * TK)         // 128 candidates per (b,g)

// Candidate buffer: per (b,g), 128 contiguous (q, idx-as-float) pairs. 2 MB.
__device__ float2 g_cand[NBG * NCAND];

// ── (q, idx) total order: value desc, index asc (jax.lax.top_k stable) ──────
__device__ __forceinline__ bool better(float av, int ai, float bv, int bi) {
    return (av > bv) || (av == bv && ai < bi);
}
__device__ __forceinline__ void ce(float &av, int &ai, float &bv, int &bi) {
    if (!better(av, ai, bv, bi)) {
        float tv = av; av = bv; bv = tv;
        int   ti = ai; ai = bi; bi = ti;
    }
}
__device__ __forceinline__ void merge4(float v[TK], int ix[TK],
                                       const float pv[TK], const int pix[TK]) {
    float s4 = pv[3], s5 = pv[2], s6 = pv[1], s7 = pv[0];
    int   t4 = pix[3], t5 = pix[2], t6 = pix[1], t7 = pix[0];
    ce(v[0], ix[0], s4, t4);  ce(v[1], ix[1], s5, t5);
    ce(v[2], ix[2], s6, t6);  ce(v[3], ix[3], s7, t7);
    ce(v[0], ix[0], v[2], ix[2]);  ce(v[1], ix[1], v[3], ix[3]);
    ce(v[0], ix[0], v[1], ix[1]);  ce(v[2], ix[2], v[3], ix[3]);
}

// ── exact-ratio order on (inter, denom, idx) triples, denom > 0 ─────────────
__device__ __forceinline__ bool betterR(float ia, float da, int xa,
                                        float ib, float db, int xb) {
    float p1 = __fmul_rn(ia, db);
    float p2 = __fmul_rn(ib, da);
    return (p1 > p2) || (p1 == p2 && xa < xb);
}
__device__ __forceinline__ void ceR(float &ia, float &da, int &xa,
                                    float &ib, float &db, int &xb) {
    if (!betterR(ia, da, xa, ib, db, xb)) {
        float t;
        t = ia; ia = ib; ib = t;
        t = da; da = db; db = t;
        int u = xa; xa = xb; xb = u;
    }
}
__device__ __forceinline__ void merge4R(float vi[TK], float vd[TK], int vx[TK],
                                        const float pi[TK], const float pd[TK],
                                        const int px[TK]) {
    float a4 = pi[3], a5 = pi[2], a6 = pi[1], a7 = pi[0];
    float b4 = pd[3], b5 = pd[2], b6 = pd[1], b7 = pd[0];
    int   c4 = px[3], c5 = px[2], c6 = px[1], c7 = px[0];
    ceR(vi[0], vd[0], vx[0], a4, b4, c4);
    ceR(vi[1], vd[1], vx[1], a5, b5, c5);
    ceR(vi[2], vd[2], vx[2], a6, b6, c6);
    ceR(vi[3], vd[3], vx[3], a7, b7, c7);
    ceR(vi[0], vd[0], vx[0], vi[2], vd[2], vx[2]);
    ceR(vi[1], vd[1], vx[1], vi[3], vd[3], vx[3]);
    ceR(vi[0], vd[0], vx[0], vi[1], vd[1], vx[1]);
    ceR(vi[2], vd[2], vx[2], vi[3], vd[3], vx[3]);
}

// ── Phase 1: per-chunk warp-level top-4 (division-free hot loop) ────────────
__global__ __launch_bounds__(NT1, 6)
void ptl_phase1(const float* __restrict__ rois,
                const float* __restrict__ targets) {
    const int blk = blockIdx.x;                  // NB*(NG/TG)*PSPLIT blocks
    const int pc  = blk % PSPLIT;
    const int t   = blk / PSPLIT;
    const int b   = t / (NG / TG);
    const int g0  = (t % (NG / TG)) * TG;
    const int tid = threadIdx.x;

    __shared__ float s_t[TG][5];   // x1,y1,x2,y2,area_t

    if (tid < TG * 4) {
        int g = tid >> 2, c = tid & 3;
        s_t[g][c] = targets[((size_t)b * NG + (g0 + g)) * 4 + c];
    }
    __syncthreads();
    if (tid < TG) {
        s_t[tid][4] = __fmul_rn(s_t[tid][2] - s_t[tid][0],
                                s_t[tid][3] - s_t[tid][1]);
    }
    __syncthreads();

    float tx1[TG], ty1[TG], tx2[TG], ty2[TG], tar[TG];
#pragma unroll
    for (int g = 0; g < TG; g++) {
        tx1[g] = s_t[g][0]; ty1[g] = s_t[g][1];
        tx2[g] = s_t[g][2]; ty2[g] = s_t[g][3];
        tar[g] = s_t[g][4];
    }

    // Top-4 as (inter, denom, idx) triples; sentinel ratio = -1/1.
    float Li[TG][TK], Ld[TG][TK];
    int   Lx[TG][TK];
#pragma unroll
    for (int g = 0; g < TG; g++)
#pragma unroll
        for (int j = 0; j < TK; j++) { Li[g][j] = -1.0f; Ld[g][j] = 1.0f; Lx[g][j] = 0x7fffffff; }

    const float4* pri = (const float4*)(rois + ((size_t)b * 2 + 1) * (size_t)NP * 4);
    const int p0 = pc * PCHUNK;
    const int PITER = PCHUNK / NT1;              // 32

    float4 cur = __ldg(&pri[p0 + tid]);
#pragma unroll 2
    for (int it = 0; it < PITER; it++) {
        const int p = p0 + tid + it * NT1;
        float4 nxt;
        if (it + 1 < PITER) nxt = __ldg(&pri[p + NT1]);

        float area_p = __fmul_rn(cur.z - cur.x, cur.w - cur.y);
#pragma unroll
        for (int g = 0; g < TG; g++) {
            float lx = fmaxf(tx1[g], cur.x);
            float ly = fmaxf(ty1[g], cur.y);
            float rx = fminf(tx2[g], cur.z);
            float ry = fminf(ty2[g], cur.w);
            float w  = fmaxf(rx - lx, 0.0f);
            float h  = fmaxf(ry - ly, 0.0f);
            float inter = __fmul_rn(w, h);
            float denom = (tar[g] + area_p) - inter;
            // Exact-ratio compare vs current 4th place (no division).
            float t1 = __fmul_rn(inter, Ld[g][3]);
            float t2 = __fmul_rn(Li[g][3], denom);
            if (t1 > t2) {   // strict: later (higher) idx loses ties
                float u1 = __fmul_rn(inter, Ld[g][2]);
                float u2 = __fmul_rn(Li[g][2], denom);
                if (u1 > u2) {
                    Li[g][3] = Li[g][2]; Ld[g][3] = Ld[g][2]; Lx[g][3] = Lx[g][2];
                    float v1 = __fmul_rn(inter, Ld[g][1]);
                    float v2 = __fmul_rn(Li[g][1], denom);
                    if (v1 > v2) {
                        Li[g][2] = Li[g][1]; Ld[g][2] = Ld[g][1]; Lx[g][2] = Lx[g][1];
                        float w1 = __fmul_rn(inter, Ld[g][0]);
                        float w2 = __fmul_rn(Li[g][0], denom);
                        if (w1 > w2) {
                            Li[g][1] = Li[g][0]; Ld[g][1] = Ld[g][0]; Lx[g][1] = Lx[g][0];
                            Li[g][0] = inter; Ld[g][0] = denom; Lx[g][0] = p;
                        } else { Li[g][1] = inter; Ld[g][1] = denom; Lx[g][1] = p; }
                    } else { Li[g][2] = inter; Ld[g][2] = denom; Lx[g][2] = p; }
                } else { Li[g][3] = inter; Ld[g][3] = denom; Lx[g][3] = p; }
            }
        }
        cur = nxt;
    }

    const int lane = tid & 31;
    const int wid  = tid >> 5;
    const int bgbase = b * NG + g0;

    // Warp-level merge per truth; lane 0 divides the 4 survivors and writes.
#pragma unroll
    for (int g = 0; g < TG; g++) {
        float vi[TK], vd[TK]; int vx[TK];
#pragma unroll
        for (int j = 0; j < TK; j++) { vi[j] = Li[g][j]; vd[j] = Ld[g][j]; vx[j] = Lx[g][j]; }
#pragma unroll
        for (int off = 16; off >= 1; off >>= 1) {
            float pi[TK], pd[TK]; int px[TK];
#pragma unroll
            for (int j = 0; j < TK; j++) {
                pi[j] = __shfl_down_sync(0xffffffffu, vi[j], off);
                pd[j] = __shfl_down_sync(0xffffffffu, vd[j], off);
                px[j] = __shfl_down_sync(0xffffffffu, vx[j], off);
            }
            merge4R(vi, vd, vx, pi, pd, px);
        }
        if (lane == 0) {
            float2* dst = g_cand + (size_t)(bgbase + g) * NCAND
                        + (pc * NWARPS1 + wid) * TK;
#pragma unroll
            for (int j = 0; j < TK; j++) {
                // jax-bit-exact IoU for survivors only
                float q = (vx[j] == 0x7fffffff) ? -1e30f
                                                : __fdiv_rn(vi[j], vd[j]);
                dst[j] = make_float2(q, __int_as_float(vx[j]));
            }
        }
    }
}

// ── Phase 2: warp per (b,g): merge 128 candidates, encode, store ────────────
__global__ __launch_bounds__(128)
void ptl_phase2(const float* __restrict__ rois,
                const float* __restrict__ targets,
                float* __restrict__ out) {
    const int lane = threadIdx.x & 31;
    const int wid  = threadIdx.x >> 5;
    const int bg   = blockIdx.x * 4 + wid;     // 0..NBG-1
    const int b    = bg / NG;

    // 128 candidates = 32 lanes x 4; two coalesced float4 (=2x float2) loads.
    const float4* cand = (const float4*)(g_cand + (size_t)bg * NCAND);
    float4 c0 = cand[lane];          // candidates 2*lane, 2*lane+1
    float4 c1 = cand[lane + 32];     // candidates 64+2*lane, 64+2*lane+1

    float v[TK]; int ix[TK];
#pragma unroll
    for (int j = 0; j < TK; j++) { v[j] = -1e30f; ix[j] = 0x7fffffff; }

    float qs[4]  = {c0.x, c0.z, c1.x, c1.z};
    int   qis[4] = {__float_as_int(c0.y), __float_as_int(c0.w),
                    __float_as_int(c1.y), __float_as_int(c1.w)};
#pragma unroll
    for (int c = 0; c < 4; c++) {
        float q = qs[c]; int qi = qis[c];
        if (better(q, qi, v[3], ix[3])) {
            if (better(q, qi, v[2], ix[2])) {
                v[3] = v[2]; ix[3] = ix[2];
                if (better(q, qi, v[1], ix[1])) {
                    v[2] = v[1]; ix[2] = ix[1];
                    if (better(q, qi, v[0], ix[0])) {
                        v[1] = v[0]; ix[1] = ix[0];
                        v[0] = q; ix[0] = qi;
                    } else { v[1] = q; ix[1] = qi; }
                } else { v[2] = q; ix[2] = qi; }
            } else { v[3] = q; ix[3] = qi; }
        }
    }

#pragma unroll
    for (int off = 16; off >= 1; off >>= 1) {
        float pv[TK]; int px[TK];
#pragma unroll
        for (int j = 0; j < TK; j++) {
            pv[j] = __shfl_down_sync(0xffffffffu, v[j],  off);
            px[j] = __shfl_down_sync(0xffffffffu, ix[j], off);
        }
        merge4(v, ix, pv, px);
    }

    // Broadcast winners; lanes 0..3 each encode one output row.
    int b0 = __shfl_sync(0xffffffffu, ix[0], 0);
    int b1 = __shfl_sync(0xffffffffu, ix[1], 0);
    int b2 = __shfl_sync(0xffffffffu, ix[2], 0);
    int b3 = __shfl_sync(0xffffffffu, ix[3], 0);

    if (lane < TK) {
        int p = b0;
        if (lane == 1) p = b1;
        if (lane == 2) p = b2;
        if (lane == 3) p = b3;

        const float4* pri = (const float4*)(rois + ((size_t)b * 2 + 1) * (size_t)NP * 4);
        float4 pr = __ldg(&pri[p]);

        float gx1 = targets[(size_t)bg * 4 + 0];
        float gy1 = targets[(size_t)bg * 4 + 1];
        float gx2 = targets[(size_t)bg * 4 + 2];
        float gy2 = targets[(size_t)bg * 4 + 3];

        float pcx = (pr.x + pr.z) * 0.5f;
        float pcy = (pr.y + pr.w) * 0.5f;
        float pw  = pr.z - pr.x;
        float ph  = pr.w - pr.y;
        float gcx = (gx1 + gx2) * 0.5f;
        float gcy = (gy1 + gy2) * 0.5f;
        float gw  = gx2 - gx1;
        float gh  = gy2 - gy1;

        float4 o;
        o.x = (gcx - pcx) / (0.1f * pw);
        o.y = (gcy - pcy) / (0.1f * ph);
        o.z = logf(gw / pw) / 0.2f;
        o.w = logf(gh / ph) / 0.2f;
        ((float4*)out)[(size_t)bg * TK + lane] = o;
    }
}

extern "C" void kernel_launch(void* const* d_in, const int* in_sizes, int n_in,
                              void* d_out, int out_size) {
    const float* rois    = (const float*)d_in[0];   // (16, 2, 32768, 4) f32
    const float* targets = (const float*)d_in[1];   // (16, 128, 4) f32
    float* out           = (float*)d_out;           // (16, 512, 4) f32
    (void)in_sizes; (void)n_in; (void)out_size;

    ptl_phase1<<<NB * (NG / TG) * PSPLIT, NT1>>>(rois, targets);
    ptl_phase2<<<NBG / 4, 128>>>(rois, targets, out);
}

// round 6
// speedup vs baseline: 2.0266x; 2.0266x over previous
#include <cuda_runtime.h>
#include <math.h>

// Problem constants (fixed by setup_inputs)
#define NB 16
#define NP 32768
#define NG 128
#define TK 4                         // top-k (expand_num)
#define PSPLIT 32                    // prior-dimension split
#define PCHUNK (NP / PSPLIT)         // 1024 priors per block
#define NT1 128                      // block = 4 warps = all 128 truths
#define NBG (NB * NG)                // 2048 (b,g) pairs
#define NCAND (PSPLIT * TK)          // 128 candidates per (b,g)

// Candidate buffer: per (b,g), 128 contiguous (q, idx-as-float) pairs. 2 MB.
__device__ float2 g_cand[NBG * NCAND];

// ── (q, idx) total order: value desc, index asc (jax.lax.top_k stable) ──────
__device__ __forceinline__ bool better(float av, int ai, float bv, int bi) {
    return (av > bv) || (av == bv && ai < bi);
}
__device__ __forceinline__ void ce(float &av, int &ai, float &bv, int &bi) {
    if (!better(av, ai, bv, bi)) {
        float tv = av; av = bv; bv = tv;
        int   ti = ai; ai = bi; bi = ti;
    }
}
__device__ __forceinline__ void merge4(float v[TK], int ix[TK],
                                       const float pv[TK], const int pix[TK]) {
    float s4 = pv[3], s5 = pv[2], s6 = pv[1], s7 = pv[0];
    int   t4 = pix[3], t5 = pix[2], t6 = pix[1], t7 = pix[0];
    ce(v[0], ix[0], s4, t4);  ce(v[1], ix[1], s5, t5);
    ce(v[2], ix[2], s6, t6);  ce(v[3], ix[3], s7, t7);
    ce(v[0], ix[0], v[2], ix[2]);  ce(v[1], ix[1], v[3], ix[3]);
    ce(v[0], ix[0], v[1], ix[1]);  ce(v[2], ix[2], v[3], ix[3]);
}

// ── Phase 1: one truth per lane; block = (image b, prior chunk pc) ──────────
__global__ __launch_bounds__(NT1)
void ptl_phase1(const float* __restrict__ rois,
                const float* __restrict__ targets) {
    const int blk = blockIdx.x;              // NB * PSPLIT blocks
    const int b   = blk / PSPLIT;
    const int pc  = blk % PSPLIT;
    const int tid = threadIdx.x;
    const int g   = tid;                     // lane's truth: g = tid (0..127)

    __shared__ float4 s_pri[PCHUNK];         // 16 KB

    // Stage this chunk's priors (coalesced float4).
    const float4* pri = (const float4*)(rois + ((size_t)b * 2 + 1) * (size_t)NP * 4);
    const int p0 = pc * PCHUNK;
#pragma unroll
    for (int j = 0; j < PCHUNK / NT1; j++)
        s_pri[tid + j * NT1] = __ldg(&pri[p0 + tid + j * NT1]);

    // My truth box (coalesced float4 across lanes).
    float4 tb = __ldg(&((const float4*)targets)[(size_t)b * NG + g]);
    const float tx1 = tb.x, ty1 = tb.y, tx2 = tb.z, ty2 = tb.w;
    const float tar = __fmul_rn(tx2 - tx1, ty2 - ty1);   // rounded once (jax)

    __syncthreads();

    // Top-4 as (inter, denom, idx); exact-ratio order via cross-multiplication.
    // Sentinel ratio = -1/1 (any real IoU in [0,1] beats it).
    float Li0 = -1.0f, Li1 = -1.0f, Li2 = -1.0f, Li3 = -1.0f;
    float Ld0 =  1.0f, Ld1 =  1.0f, Ld2 =  1.0f, Ld3 =  1.0f;
    int   Lx0 = 0x7fffffff, Lx1 = 0x7fffffff, Lx2 = 0x7fffffff, Lx3 = 0x7fffffff;

#pragma unroll 4
    for (int i = 0; i < PCHUNK; i++) {
        float4 pr = s_pri[i];                // LDS.128 broadcast (N=1)
        float area_p = __fmul_rn(pr.z - pr.x, pr.w - pr.y);
        float lx = fmaxf(tx1, pr.x);
        float ly = fmaxf(ty1, pr.y);
        float rx = fminf(tx2, pr.z);
        float ry = fminf(ty2, pr.w);
        float w  = fmaxf(rx - lx, 0.0f);
        float h  = fmaxf(ry - ly, 0.0f);
        float inter = __fmul_rn(w, h);
        float denom = (tar + area_p) - inter;

        // Gate vs 4th place (strict >: product tie keeps earlier index).
        bool c3 = __fmul_rn(inter, Ld3) > __fmul_rn(Li3, denom);
        if (c3) {
            // Branchless select-insert. List sorted desc, so c0 => c1 => c2.
            bool c2 = __fmul_rn(inter, Ld2) > __fmul_rn(Li2, denom);
            bool c1 = __fmul_rn(inter, Ld1) > __fmul_rn(Li1, denom);
            bool c0 = __fmul_rn(inter, Ld0) > __fmul_rn(Li0, denom);
            Li3 = c2 ? Li2 : inter;  Ld3 = c2 ? Ld2 : denom;  Lx3 = c2 ? Lx2 : i;
            Li2 = c1 ? Li1 : (c2 ? inter : Li2);
            Ld2 = c1 ? Ld1 : (c2 ? denom : Ld2);
            Lx2 = c1 ? Lx1 : (c2 ? i     : Lx2);
            Li1 = c0 ? Li0 : (c1 ? inter : Li1);
            Ld1 = c0 ? Ld0 : (c1 ? denom : Ld1);
            Lx1 = c0 ? Lx0 : (c1 ? i     : Lx1);
            Li0 = c0 ? inter : Li0;
            Ld0 = c0 ? denom : Ld0;
            Lx0 = c0 ? i     : Lx0;
        }
    }

    // Epilogue: exact jax-bit IoU for the 4 survivors only; write candidates.
    float2* dst = g_cand + (size_t)(b * NG + g) * NCAND + pc * TK;
    float q0 = (Lx0 == 0x7fffffff) ? -1e30f : __fdiv_rn(Li0, Ld0);
    float q1 = (Lx1 == 0x7fffffff) ? -1e30f : __fdiv_rn(Li1, Ld1);
    float q2 = (Lx2 == 0x7fffffff) ? -1e30f : __fdiv_rn(Li2, Ld2);
    float q3 = (Lx3 == 0x7fffffff) ? -1e30f : __fdiv_rn(Li3, Ld3);
    int i0 = (Lx0 == 0x7fffffff) ? 0x7fffffff : p0 + Lx0;
    int i1 = (Lx1 == 0x7fffffff) ? 0x7fffffff : p0 + Lx1;
    int i2 = (Lx2 == 0x7fffffff) ? 0x7fffffff : p0 + Lx2;
    int i3 = (Lx3 == 0x7fffffff) ? 0x7fffffff : p0 + Lx3;
    dst[0] = make_float2(q0, __int_as_float(i0));
    dst[1] = make_float2(q1, __int_as_float(i1));
    dst[2] = make_float2(q2, __int_as_float(i2));
    dst[3] = make_float2(q3, __int_as_float(i3));
}

// ── Phase 2: warp per (b,g): merge 128 candidates, encode, store ────────────
__global__ __launch_bounds__(128)
void ptl_phase2(const float* __restrict__ rois,
                const float* __restrict__ targets,
                float* __restrict__ out) {
    const int lane = threadIdx.x & 31;
    const int wid  = threadIdx.x >> 5;
    const int bg   = blockIdx.x * 4 + wid;     // 0..NBG-1
    const int b    = bg / NG;

    // 128 candidates = 32 lanes x 4; two coalesced float4 (=2x float2) loads.
    const float4* cand = (const float4*)(g_cand + (size_t)bg * NCAND);
    float4 c0 = cand[lane];          // candidates 2*lane, 2*lane+1
    float4 c1 = cand[lane + 32];     // candidates 64+2*lane, 64+2*lane+1

    float v[TK]; int ix[TK];
#pragma unroll
    for (int j = 0; j < TK; j++) { v[j] = -1e30f; ix[j] = 0x7fffffff; }

    float qs[4]  = {c0.x, c0.z, c1.x, c1.z};
    int   qis[4] = {__float_as_int(c0.y), __float_as_int(c0.w),
                    __float_as_int(c1.y), __float_as_int(c1.w)};
#pragma unroll
    for (int c = 0; c < 4; c++) {
        float q = qs[c]; int qi = qis[c];
        if (better(q, qi, v[3], ix[3])) {
            if (better(q, qi, v[2], ix[2])) {
                v[3] = v[2]; ix[3] = ix[2];
                if (better(q, qi, v[1], ix[1])) {
                    v[2] = v[1]; ix[2] = ix[1];
                    if (better(q, qi, v[0], ix[0])) {
                        v[1] = v[0]; ix[1] = ix[0];
                        v[0] = q; ix[0] = qi;
                    } else { v[1] = q; ix[1] = qi; }
                } else { v[2] = q; ix[2] = qi; }
            } else { v[3] = q; ix[3] = qi; }
        }
    }

#pragma unroll
    for (int off = 16; off >= 1; off >>= 1) {
        float pv[TK]; int px[TK];
#pragma unroll
        for (int j = 0; j < TK; j++) {
            pv[j] = __shfl_down_sync(0xffffffffu, v[j],  off);
            px[j] = __shfl_down_sync(0xffffffffu, ix[j], off);
        }
        merge4(v, ix, pv, px);
    }

    // Broadcast winners; lanes 0..3 each encode one output row.
    int b0 = __shfl_sync(0xffffffffu, ix[0], 0);
    int b1 = __shfl_sync(0xffffffffu, ix[1], 0);
    int b2 = __shfl_sync(0xffffffffu, ix[2], 0);
    int b3 = __shfl_sync(0xffffffffu, ix[3], 0);

    if (lane < TK) {
        int p = b0;
        if (lane == 1) p = b1;
        if (lane == 2) p = b2;
        if (lane == 3) p = b3;

        const float4* pri = (const float4*)(rois + ((size_t)b * 2 + 1) * (size_t)NP * 4);
        float4 pr = __ldg(&pri[p]);

        float gx1 = targets[(size_t)bg * 4 + 0];
        float gy1 = targets[(size_t)bg * 4 + 1];
        float gx2 = targets[(size_t)bg * 4 + 2];
        float gy2 = targets[(size_t)bg * 4 + 3];

        float pcx = (pr.x + pr.z) * 0.5f;
        float pcy = (pr.y + pr.w) * 0.5f;
        float pw  = pr.z - pr.x;
        float ph  = pr.w - pr.y;
        float gcx = (gx1 + gx2) * 0.5f;
        float gcy = (gy1 + gy2) * 0.5f;
        float gw  = gx2 - gx1;
        float gh  = gy2 - gy1;

        float4 o;
        o.x = (gcx - pcx) / (0.1f * pw);
        o.y = (gcy - pcy) / (0.1f * ph);
        o.z = logf(gw / pw) / 0.2f;
        o.w = logf(gh / ph) / 0.2f;
        ((float4*)out)[(size_t)bg * TK + lane] = o;
    }
}

extern "C" void kernel_launch(void* const* d_in, const int* in_sizes, int n_in,
                              void* d_out, int out_size) {
    const float* rois    = (const float*)d_in[0];   // (16, 2, 32768, 4) f32
    const float* targets = (const float*)d_in[1];   // (16, 128, 4) f32
    float* out           = (float*)d_out;           // (16, 512, 4) f32
    (void)in_sizes; (void)n_in; (void)out_size;

    ptl_phase1<<<NB * PSPLIT, NT1>>>(rois, targets);
    ptl_phase2<<<NBG / 4, 128>>>(rois, targets, out);
}

// round 8
// speedup vs baseline: 2.0324x; 1.0029x over previous
#include <cuda_runtime.h>
#include <math.h>

// Problem constants (fixed by setup_inputs)
#define NB 16
#define NP 32768
#define NG 128
#define TK 4                         // top-k (expand_num)
#define PSPLIT 64                    // prior-dimension split
#define PCHUNK (NP / PSPLIT)         // 512 priors per block
#define NT1 128                      // block = 4 warps = all 128 truths
#define NBG (NB * NG)                // 2048 (b,g) pairs
#define NCAND (PSPLIT * TK)          // 256 candidates per (b,g)

// Candidate buffer: per (b,g), 256 contiguous (q, idx-as-float) pairs. 4 MB.
__device__ float2 g_cand[NBG * NCAND];

// ── (q, idx) total order: value desc, index asc (jax.lax.top_k stable) ──────
__device__ __forceinline__ bool better(float av, int ai, float bv, int bi) {
    return (av > bv) || (av == bv && ai < bi);
}
__device__ __forceinline__ void ce(float &av, int &ai, float &bv, int &bi) {
    if (!better(av, ai, bv, bi)) {
        float tv = av; av = bv; bv = tv;
        int   ti = ai; ai = bi; bi = ti;
    }
}
__device__ __forceinline__ void merge4(float v[TK], int ix[TK],
                                       const float pv[TK], const int pix[TK]) {
    float s4 = pv[3], s5 = pv[2], s6 = pv[1], s7 = pv[0];
    int   t4 = pix[3], t5 = pix[2], t6 = pix[1], t7 = pix[0];
    ce(v[0], ix[0], s4, t4);  ce(v[1], ix[1], s5, t5);
    ce(v[2], ix[2], s6, t6);  ce(v[3], ix[3], s7, t7);
    ce(v[0], ix[0], v[2], ix[2]);  ce(v[1], ix[1], v[3], ix[3]);
    ce(v[0], ix[0], v[1], ix[1]);  ce(v[2], ix[2], v[3], ix[3]);
}

// ── Phase 1: one truth per lane; block = (image b, prior chunk pc) ──────────
__global__ __launch_bounds__(NT1)
void ptl_phase1(const float* __restrict__ rois,
                const float* __restrict__ targets) {
    const int blk = blockIdx.x;              // NB * PSPLIT blocks
    const int b   = blk / PSPLIT;
    const int pc  = blk % PSPLIT;
    const int tid = threadIdx.x;
    const int g   = tid;                     // lane's truth: g = tid (0..127)

    __shared__ float4 s_pri[PCHUNK];         // 8 KB
    __shared__ float  s_area[PCHUNK];        // 2 KB: prior areas (lane-invariant)

    // Stage this chunk's priors + areas (coalesced float4).
    const float4* pri = (const float4*)(rois + ((size_t)b * 2 + 1) * (size_t)NP * 4);
    const int p0 = pc * PCHUNK;
#pragma unroll
    for (int j = 0; j < PCHUNK / NT1; j++) {
        float4 pr = __ldg(&pri[p0 + tid + j * NT1]);
        s_pri[tid + j * NT1]  = pr;
        s_area[tid + j * NT1] = __fmul_rn(pr.z - pr.x, pr.w - pr.y); // jax rounding
    }

    // My truth box (coalesced float4 across lanes).
    float4 tb = __ldg(&((const float4*)targets)[(size_t)b * NG + g]);
    const float tx1 = tb.x, ty1 = tb.y, tx2 = tb.z, ty2 = tb.w;
    const float tar = __fmul_rn(tx2 - tx1, ty2 - ty1);   // rounded once (jax)

    __syncthreads();

    // Top-4 as (inter, denom, idx); exact-ratio order via cross-multiplication.
    // Sentinel ratio = -1/1 (any real IoU in [0,1] beats it).
    float Li0 = -1.0f, Li1 = -1.0f, Li2 = -1.0f, Li3 = -1.0f;
    float Ld0 =  1.0f, Ld1 =  1.0f, Ld2 =  1.0f, Ld3 =  1.0f;
    int   Lx0 = 0x7fffffff, Lx1 = 0x7fffffff, Lx2 = 0x7fffffff, Lx3 = 0x7fffffff;

#pragma unroll 4
    for (int i = 0; i < PCHUNK; i++) {
        float4 pr = s_pri[i];                // LDS.128 broadcast (N=1)
        float area_p = s_area[i];            // LDS.32 broadcast
        float lx = fmaxf(tx1, pr.x);
        float ly = fmaxf(ty1, pr.y);
        float rx = fminf(tx2, pr.z);
        float ry = fminf(ty2, pr.w);
        float w  = fmaxf(rx - lx, 0.0f);
        float h  = fmaxf(ry - ly, 0.0f);
        float inter = __fmul_rn(w, h);
        float denom = (tar + area_p) - inter;

        // Gate vs 4th place (strict >: product tie keeps earlier index).
        bool c3 = __fmul_rn(inter, Ld3) > __fmul_rn(Li3, denom);
        if (c3) {
            // Branchless select-insert. List sorted desc, so c0 => c1 => c2.
            bool c2 = __fmul_rn(inter, Ld2) > __fmul_rn(Li2, denom);
            bool c1 = __fmul_rn(inter, Ld1) > __fmul_rn(Li1, denom);
            bool c0 = __fmul_rn(inter, Ld0) > __fmul_rn(Li0, denom);
            Li3 = c2 ? Li2 : inter;  Ld3 = c2 ? Ld2 : denom;  Lx3 = c2 ? Lx2 : i;
            Li2 = c1 ? Li1 : (c2 ? inter : Li2);
            Ld2 = c1 ? Ld1 : (c2 ? denom : Ld2);
            Lx2 = c1 ? Lx1 : (c2 ? i     : Lx2);
            Li1 = c0 ? Li0 : (c1 ? inter : Li1);
            Ld1 = c0 ? Ld0 : (c1 ? denom : Ld1);
            Lx1 = c0 ? Lx0 : (c1 ? i     : Lx1);
            Li0 = c0 ? inter : Li0;
            Ld0 = c0 ? denom : Ld0;
            Lx0 = c0 ? i     : Lx0;
        }
    }

    // Epilogue: exact jax-bit IoU for the 4 survivors only; write candidates.
    float2* dst = g_cand + (size_t)(b * NG + g) * NCAND + pc * TK;
    float q0 = (Lx0 == 0x7fffffff) ? -1e30f : __fdiv_rn(Li0, Ld0);
    float q1 = (Lx1 == 0x7fffffff) ? -1e30f : __fdiv_rn(Li1, Ld1);
    float q2 = (Lx2 == 0x7fffffff) ? -1e30f : __fdiv_rn(Li2, Ld2);
    float q3 = (Lx3 == 0x7fffffff) ? -1e30f : __fdiv_rn(Li3, Ld3);
    int i0 = (Lx0 == 0x7fffffff) ? 0x7fffffff : p0 + Lx0;
    int i1 = (Lx1 == 0x7fffffff) ? 0x7fffffff : p0 + Lx1;
    int i2 = (Lx2 == 0x7fffffff) ? 0x7fffffff : p0 + Lx2;
    int i3 = (Lx3 == 0x7fffffff) ? 0x7fffffff : p0 + Lx3;
    dst[0] = make_float2(q0, __int_as_float(i0));
    dst[1] = make_float2(q1, __int_as_float(i1));
    dst[2] = make_float2(q2, __int_as_float(i2));
    dst[3] = make_float2(q3, __int_as_float(i3));
}

// ── Phase 2: warp per (b,g): merge 256 candidates, encode, store ────────────
__global__ __launch_bounds__(128)
void ptl_phase2(const float* __restrict__ rois,
                const float* __restrict__ targets,
                float* __restrict__ out) {
    const int lane = threadIdx.x & 31;
    const int wid  = threadIdx.x >> 5;
    const int bg   = blockIdx.x * 4 + wid;     // 0..NBG-1
    const int b    = bg / NG;

    // 256 candidates = 32 lanes x 8; four coalesced float4 (=2x float2) loads.
    const float4* cand = (const float4*)(g_cand + (size_t)bg * NCAND);

    float v[TK]; int ix[TK];
#pragma unroll
    for (int j = 0; j < TK; j++) { v[j] = -1e30f; ix[j] = 0x7fffffff; }

#pragma unroll
    for (int blkc = 0; blkc < 4; blkc++) {
        float4 c = cand[lane + blkc * 32];
        float qs[2]  = {c.x, c.z};
        int   qis[2] = {__float_as_int(c.y), __float_as_int(c.w)};
#pragma unroll
        for (int t = 0; t < 2; t++) {
            float q = qs[t]; int qi = qis[t];
            if (better(q, qi, v[3], ix[3])) {
                if (better(q, qi, v[2], ix[2])) {
                    v[3] = v[2]; ix[3] = ix[2];
                    if (better(q, qi, v[1], ix[1])) {
                        v[2] = v[1]; ix[2] = ix[1];
                        if (better(q, qi, v[0], ix[0])) {
                            v[1] = v[0]; ix[1] = ix[0];
                            v[0] = q; ix[0] = qi;
                        } else { v[1] = q; ix[1] = qi; }
                    } else { v[2] = q; ix[2] = qi; }
                } else { v[3] = q; ix[3] = qi; }
            }
        }
    }

#pragma unroll
    for (int off = 16; off >= 1; off >>= 1) {
        float pv[TK]; int px[TK];
#pragma unroll
        for (int j = 0; j < TK; j++) {
            pv[j] = __shfl_down_sync(0xffffffffu, v[j],  off);
            px[j] = __shfl_down_sync(0xffffffffu, ix[j], off);
        }
        merge4(v, ix, pv, px);
    }

    // Broadcast winners; lanes 0..3 each encode one output row.
    int b0 = __shfl_sync(0xffffffffu, ix[0], 0);
    int b1 = __shfl_sync(0xffffffffu, ix[1], 0);
    int b2 = __shfl_sync(0xffffffffu, ix[2], 0);
    int b3 = __shfl_sync(0xffffffffu, ix[3], 0);

    if (lane < TK) {
        int p = b0;
        if (lane == 1) p = b1;
        if (lane == 2) p = b2;
        if (lane == 3) p = b3;

        const float4* pri = (const float4*)(rois + ((size_t)b * 2 + 1) * (size_t)NP * 4);
        float4 pr = __ldg(&pri[p]);

        float gx1 = targets[(size_t)bg * 4 + 0];
        float gy1 = targets[(size_t)bg * 4 + 1];
        float gx2 = targets[(size_t)bg * 4 + 2];
        float gy2 = targets[(size_t)bg * 4 + 3];

        float pcx = (pr.x + pr.z) * 0.5f;
        float pcy = (pr.y + pr.w) * 0.5f;
        float pw  = pr.z - pr.x;
        float ph  = pr.w - pr.y;
        float gcx = (gx1 + gx2) * 0.5f;
        float gcy = (gy1 + gy2) * 0.5f;
        float gw  = gx2 - gx1;
        float gh  = gy2 - gy1;

        float4 o;
        o.x = (gcx - pcx) / (0.1f * pw);
        o.y = (gcy - pcy) / (0.1f * ph);
        o.z = logf(gw / pw) / 0.2f;
        o.w = logf(gh / ph) / 0.2f;
        ((float4*)out)[(size_t)bg * TK + lane] = o;
    }
}

extern "C" void kernel_launch(void* const* d_in, const int* in_sizes, int n_in,
                              void* d_out, int out_size) {
    const float* rois    = (const float*)d_in[0];   // (16, 2, 32768, 4) f32
    const float* targets = (const float*)d_in[1];   // (16, 128, 4) f32
    float* out           = (float*)d_out;           // (16, 512, 4) f32
    (void)in_sizes; (void)n_in; (void)out_size;

    ptl_phase1<<<NB * PSPLIT, NT1>>>(rois, targets);
    ptl_phase2<<<NBG / 4, 128>>>(rois, targets, out);
}

// round 9
// speedup vs baseline: 2.2621x; 1.1130x over previous
#include <cuda_runtime.h>
#include <math.h>

// Problem constants (fixed by setup_inputs)
#define NB 16
#define NP 32768
#define NG 128
#define TK 4                     // top-k (expand_num)
#define CSPLIT 2                 // chunks per image (warps per truth)
#define WPB 8                    // warps (=truths) per block
#define NT1 (WPB * 32)           // 256 threads
#define CHUNK (NP / CSPLIT)      // 16384 priors per warp-stream
#define TILE 2048                // smem tile of priors
#define NTILES (CHUNK / TILE)    // 8
#define ITERS (TILE / 32)        // 64 warp-iters per tile
#define NBG (NB * NG)            // 2048 truths total
#define NCPT (CSPLIT * TK)       // 8 candidates per truth

// Candidate buffer: per truth, 8 (q, idx-as-float) pairs. 128 KB.
__device__ float2 g_cand[NBG * NCPT];

// ── (q, idx) total order: value desc, index asc (jax.lax.top_k stable) ──────
__device__ __forceinline__ bool better(float av, int ai, float bv, int bi) {
    return (av > bv) || (av == bv && ai < bi);
}

// ── Phase 1: warp = one truth; lanes stride priors; replicated top-4 ────────
__global__ __launch_bounds__(NT1)
void ptl_phase1(const float* __restrict__ rois,
                const float* __restrict__ targets) {
    const int nTGrp = NG / WPB;                    // 16 truth-groups per image
    const int blk  = blockIdx.x;                   // NB * nTGrp * CSPLIT = 512
    const int b    = blk / (nTGrp * CSPLIT);
    const int rem  = blk % (nTGrp * CSPLIT);
    const int tg   = rem / CSPLIT;
    const int cs   = rem % CSPLIT;
    const int tid  = threadIdx.x;
    const int lane = tid & 31;
    const int w    = tid >> 5;
    const int g    = tg * WPB + w;                 // this warp's truth

    __shared__ float4 s_pri[TILE];                 // 32 KB
    __shared__ float  s_area[TILE];                // 8 KB

    // My warp's truth box (uniform across lanes; L1-broadcast).
    float4 tb = __ldg(&((const float4*)targets)[(size_t)b * NG + g]);
    const float tx1 = tb.x, ty1 = tb.y, tx2 = tb.z, ty2 = tb.w;
    const float tar = __fmul_rn(tx2 - tx1, ty2 - ty1);    // rounded once (jax)

    // Warp-replicated top-4 as (inter, denom, idx); sentinel ratio = -1/1.
    float Li0 = -1.0f, Li1 = -1.0f, Li2 = -1.0f, Li3 = -1.0f;
    float Ld0 =  1.0f, Ld1 =  1.0f, Ld2 =  1.0f, Ld3 =  1.0f;
    int   Lx0 = 0x7fffffff, Lx1 = 0x7fffffff, Lx2 = 0x7fffffff, Lx3 = 0x7fffffff;

    const float4* pri = (const float4*)(rois + ((size_t)b * 2 + 1) * (size_t)NP * 4);

    for (int tile = 0; tile < NTILES; tile++) {
        const int base = cs * CHUNK + tile * TILE;

        // Cooperative stage: 256 threads x 8 float4 each.
#pragma unroll
        for (int k = tid; k < TILE; k += NT1) {
            float4 pr = __ldg(&pri[base + k]);
            s_pri[k]  = pr;
            s_area[k] = __fmul_rn(pr.z - pr.x, pr.w - pr.y);   // jax rounding
        }
        __syncthreads();

#pragma unroll 4
        for (int i = 0; i < ITERS; i++) {
            const int j = i * 32 + lane;
            float4 pr   = s_pri[j];              // LDS.128, conflict-free
            float area_p = s_area[j];            // LDS.32, conflict-free
            float lx = fmaxf(tx1, pr.x);
            float ly = fmaxf(ty1, pr.y);
            float rx = fminf(tx2, pr.z);
            float ry = fminf(ty2, pr.w);
            float wd = fmaxf(rx - lx, 0.0f);
            float ht = fmaxf(ry - ly, 0.0f);
            float inter = __fmul_rn(wd, ht);
            float denom = (tar + area_p) - inter;

            // Per-lane gate vs warp's current 4th (strict >, cross-mult).
            bool pass = __fmul_rn(inter, Ld3) > __fmul_rn(Li3, denom);
            unsigned m = __ballot_sync(0xffffffffu, pass);
            while (m) {                          // uniform loop (rare)
                int l = __ffs(m) - 1; m &= m - 1;
                float ci = __shfl_sync(0xffffffffu, inter, l);
                float cd = __shfl_sync(0xffffffffu, denom, l);
                int   cx = base + i * 32 + l;    // global prior index (uniform)
                // Re-check vs (possibly updated) list — uniform branch.
                bool c3 = __fmul_rn(ci, Ld3) > __fmul_rn(Li3, cd);
                if (c3) {
                    bool c2 = __fmul_rn(ci, Ld2) > __fmul_rn(Li2, cd);
                    bool c1 = __fmul_rn(ci, Ld1) > __fmul_rn(Li1, cd);
                    bool c0 = __fmul_rn(ci, Ld0) > __fmul_rn(Li0, cd);
                    Li3 = c2 ? Li2 : ci;  Ld3 = c2 ? Ld2 : cd;  Lx3 = c2 ? Lx2 : cx;
                    Li2 = c1 ? Li1 : (c2 ? ci : Li2);
                    Ld2 = c1 ? Ld1 : (c2 ? cd : Ld2);
                    Lx2 = c1 ? Lx1 : (c2 ? cx : Lx2);
                    Li1 = c0 ? Li0 : (c1 ? ci : Li1);
                    Ld1 = c0 ? Ld0 : (c1 ? cd : Ld1);
                    Lx1 = c0 ? Lx0 : (c1 ? cx : Lx1);
                    Li0 = c0 ? ci : Li0;
                    Ld0 = c0 ? cd : Ld0;
                    Lx0 = c0 ? cx : Lx0;
                }
            }
        }
        __syncthreads();
    }

    // Epilogue: lanes 0..3 each finalize one survivor (exact jax-bit IoU).
    if (lane < TK) {
        float si = (lane == 0) ? Li0 : (lane == 1) ? Li1 : (lane == 2) ? Li2 : Li3;
        float sd = (lane == 0) ? Ld0 : (lane == 1) ? Ld1 : (lane == 2) ? Ld2 : Ld3;
        int   sx = (lane == 0) ? Lx0 : (lane == 1) ? Lx1 : (lane == 2) ? Lx2 : Lx3;
        float q = (sx == 0x7fffffff) ? -1e30f : __fdiv_rn(si, sd);
        g_cand[(size_t)(b * NG + g) * NCPT + cs * TK + lane] =
            make_float2(q, __int_as_float(sx));
    }
}

// ── Phase 2: one thread per truth: merge 8 candidates, encode, store ────────
__global__ __launch_bounds__(128)
void ptl_phase2(const float* __restrict__ rois,
                const float* __restrict__ targets,
                float* __restrict__ out) {
    const int bg = blockIdx.x * 128 + threadIdx.x;   // 0..NBG-1
    const int b  = bg / NG;

    float v[TK]; int ix[TK];
#pragma unroll
    for (int j = 0; j < TK; j++) { v[j] = -1e30f; ix[j] = 0x7fffffff; }

    const float2* cand = g_cand + (size_t)bg * NCPT;
#pragma unroll
    for (int c = 0; c < NCPT; c++) {
        float2 cc = cand[c];
        float q = cc.x; int qi = __float_as_int(cc.y);
        if (better(q, qi, v[3], ix[3])) {
            if (better(q, qi, v[2], ix[2])) {
                v[3] = v[2]; ix[3] = ix[2];
                if (better(q, qi, v[1], ix[1])) {
                    v[2] = v[1]; ix[2] = ix[1];
                    if (better(q, qi, v[0], ix[0])) {
                        v[1] = v[0]; ix[1] = ix[0];
                        v[0] = q; ix[0] = qi;
                    } else { v[1] = q; ix[1] = qi; }
                } else { v[2] = q; ix[2] = qi; }
            } else { v[3] = q; ix[3] = qi; }
        }
    }

    // Encode 4 output rows (64B contiguous per thread; coalesced across warp).
    float gx1 = targets[(size_t)bg * 4 + 0];
    float gy1 = targets[(size_t)bg * 4 + 1];
    float gx2 = targets[(size_t)bg * 4 + 2];
    float gy2 = targets[(size_t)bg * 4 + 3];
    float gcx = (gx1 + gx2) * 0.5f;
    float gcy = (gy1 + gy2) * 0.5f;
    float gw  = gx2 - gx1;
    float gh  = gy2 - gy1;

    const float4* pri = (const float4*)(rois + ((size_t)b * 2 + 1) * (size_t)NP * 4);
#pragma unroll
    for (int k = 0; k < TK; k++) {
        float4 pr = __ldg(&pri[ix[k]]);
        float pcx = (pr.x + pr.z) * 0.5f;
        float pcy = (pr.y + pr.w) * 0.5f;
        float pw  = pr.z - pr.x;
        float ph  = pr.w - pr.y;
        float4 o;
        o.x = (gcx - pcx) / (0.1f * pw);
        o.y = (gcy - pcy) / (0.1f * ph);
        o.z = logf(gw / pw) / 0.2f;
        o.w = logf(gh / ph) / 0.2f;
        ((float4*)out)[(size_t)bg * TK + k] = o;
    }
}

extern "C" void kernel_launch(void* const* d_in, const int* in_sizes, int n_in,
                              void* d_out, int out_size) {
    const float* rois    = (const float*)d_in[0];   // (16, 2, 32768, 4) f32
    const float* targets = (const float*)d_in[1];   // (16, 128, 4) f32
    float* out           = (float*)d_out;           // (16, 512, 4) f32
    (void)in_sizes; (void)n_in; (void)out_size;

    ptl_phase1<<<NB * (NG / WPB) * CSPLIT, NT1>>>(rois, targets);
    ptl_phase2<<<NBG / 128, 128>>>(rois, targets, out);
}

// round 10
// speedup vs baseline: 2.4424x; 1.0797x over previous
#include <cuda_runtime.h>
#include <math.h>

// Problem constants (fixed by setup_inputs)
#define NB 16
#define NP 32768
#define NG 128
#define TK 4                     // top-k (expand_num)
#define CSPLIT 4                 // chunks per image (streams per truth)
#define WPB 8                    // warps (=truths) per block
#define NT1 (WPB * 32)           // 256 threads
#define CHUNK (NP / CSPLIT)      // 8192 priors per warp-stream
#define TILE 2048                // smem tile of priors
#define NTILES (CHUNK / TILE)    // 4
#define ITERS (TILE / 32)        // 64 warp-iters per tile
#define NBG (NB * NG)            // 2048 truths total
#define NCPT (CSPLIT * TK)       // 16 candidates per truth

// Candidate buffer: per truth, 16 (q, idx-as-float) pairs. 256 KB.
__device__ float2 g_cand[NBG * NCPT];

// ── (q, idx) total order: value desc, index asc (jax.lax.top_k stable) ──────
__device__ __forceinline__ bool better(float av, int ai, float bv, int bi) {
    return (av > bv) || (av == bv && ai < bi);
}

// ── Phase 1: warp = one truth; lanes stride priors; replicated top-4 ────────
__global__ __launch_bounds__(NT1)
void ptl_phase1(const float* __restrict__ rois,
                const float* __restrict__ targets) {
    const int nTGrp = NG / WPB;                    // 16 truth-groups per image
    const int blk  = blockIdx.x;                   // NB * nTGrp * CSPLIT = 1024
    const int b    = blk / (nTGrp * CSPLIT);
    const int rem  = blk % (nTGrp * CSPLIT);
    const int tg   = rem / CSPLIT;
    const int cs   = rem % CSPLIT;
    const int tid  = threadIdx.x;
    const int lane = tid & 31;
    const int w    = tid >> 5;
    const int g    = tg * WPB + w;                 // this warp's truth

    __shared__ float4 s_pri[TILE];                 // 32 KB

    // My warp's truth box (uniform across lanes; L1-broadcast).
    float4 tb = __ldg(&((const float4*)targets)[(size_t)b * NG + g]);
    const float tx1 = tb.x, ty1 = tb.y, tx2 = tb.z, ty2 = tb.w;
    const float tar = __fmul_rn(tx2 - tx1, ty2 - ty1);    // rounded once (jax)

    // Warp-replicated top-4 as (inter, denom, idx); sentinel ratio = -1/1.
    float Li0 = -1.0f, Li1 = -1.0f, Li2 = -1.0f, Li3 = -1.0f;
    float Ld0 =  1.0f, Ld1 =  1.0f, Ld2 =  1.0f, Ld3 =  1.0f;
    int   Lx0 = 0x7fffffff, Lx1 = 0x7fffffff, Lx2 = 0x7fffffff, Lx3 = 0x7fffffff;

    const float4* pri = (const float4*)(rois + ((size_t)b * 2 + 1) * (size_t)NP * 4);

    for (int tile = 0; tile < NTILES; tile++) {
        const int base = cs * CHUNK + tile * TILE;

        // Cooperative stage: 256 threads x 8 float4 each.
#pragma unroll
        for (int k = tid; k < TILE; k += NT1)
            s_pri[k] = __ldg(&pri[base + k]);
        __syncthreads();

#pragma unroll 4
        for (int i = 0; i < ITERS; i++) {
            const int j = i * 32 + lane;
            float4 pr = s_pri[j];                       // LDS.128, conflict-free
            float area_p = __fmul_rn(pr.z - pr.x, pr.w - pr.y);  // regs, jax bits
            float lx = fmaxf(tx1, pr.x);
            float ly = fmaxf(ty1, pr.y);
            float rx = fminf(tx2, pr.z);
            float ry = fminf(ty2, pr.w);
            float wd = fmaxf(rx - lx, 0.0f);
            float ht = fmaxf(ry - ly, 0.0f);
            float inter = __fmul_rn(wd, ht);
            float denom = (tar + area_p) - inter;

            // Per-lane gate vs warp's current 4th (strict >, cross-mult).
            bool pass = __fmul_rn(inter, Ld3) > __fmul_rn(Li3, denom);
            unsigned m = __ballot_sync(0xffffffffu, pass);
            while (m) {                          // uniform loop (rare, ~7%)
                int l = __ffs(m) - 1; m &= m - 1;
                float ci = __shfl_sync(0xffffffffu, inter, l);
                float cd = __shfl_sync(0xffffffffu, denom, l);
                int   cx = base + i * 32 + l;    // global prior index (uniform)
                // Re-check vs (possibly updated) list — uniform branch.
                bool c3 = __fmul_rn(ci, Ld3) > __fmul_rn(Li3, cd);
                if (c3) {
                    bool c2 = __fmul_rn(ci, Ld2) > __fmul_rn(Li2, cd);
                    bool c1 = __fmul_rn(ci, Ld1) > __fmul_rn(Li1, cd);
                    bool c0 = __fmul_rn(ci, Ld0) > __fmul_rn(Li0, cd);
                    Li3 = c2 ? Li2 : ci;  Ld3 = c2 ? Ld2 : cd;  Lx3 = c2 ? Lx2 : cx;
                    Li2 = c1 ? Li1 : (c2 ? ci : Li2);
                    Ld2 = c1 ? Ld1 : (c2 ? cd : Ld2);
                    Lx2 = c1 ? Lx1 : (c2 ? cx : Lx2);
                    Li1 = c0 ? Li0 : (c1 ? ci : Li1);
                    Ld1 = c0 ? Ld0 : (c1 ? cd : Ld1);
                    Lx1 = c0 ? Lx0 : (c1 ? cx : Lx1);
                    Li0 = c0 ? ci : Li0;
                    Ld0 = c0 ? cd : Ld0;
                    Lx0 = c0 ? cx : Lx0;
                }
            }
        }
        __syncthreads();
    }

    // Epilogue: lanes 0..3 each finalize one survivor (exact jax-bit IoU).
    if (lane < TK) {
        float si = (lane == 0) ? Li0 : (lane == 1) ? Li1 : (lane == 2) ? Li2 : Li3;
        float sd = (lane == 0) ? Ld0 : (lane == 1) ? Ld1 : (lane == 2) ? Ld2 : Ld3;
        int   sx = (lane == 0) ? Lx0 : (lane == 1) ? Lx1 : (lane == 2) ? Lx2 : Lx3;
        float q = (sx == 0x7fffffff) ? -1e30f : __fdiv_rn(si, sd);
        g_cand[(size_t)(b * NG + g) * NCPT + cs * TK + lane] =
            make_float2(q, __int_as_float(sx));
    }
}

// ── Phase 2: one thread per (truth, k): merge 16 candidates, encode row k ───
__global__ __launch_bounds__(128)
void ptl_phase2(const float* __restrict__ rois,
                const float* __restrict__ targets,
                float* __restrict__ out) {
    const int t  = blockIdx.x * 128 + threadIdx.x;   // 0..NBG*TK-1
    const int bg = t >> 2;
    const int k  = t & 3;
    const int b  = bg / NG;

    float v[TK]; int ix[TK];
#pragma unroll
    for (int j = 0; j < TK; j++) { v[j] = -1e30f; ix[j] = 0x7fffffff; }

    // All 4 threads of a truth read the same 16 candidates (L2/L1 broadcast).
    const float2* cand = g_cand + (size_t)bg * NCPT;
#pragma unroll
    for (int c = 0; c < NCPT; c++) {
        float2 cc = cand[c];
        float q = cc.x; int qi = __float_as_int(cc.y);
        if (better(q, qi, v[3], ix[3])) {
            if (better(q, qi, v[2], ix[2])) {
                v[3] = v[2]; ix[3] = ix[2];
                if (better(q, qi, v[1], ix[1])) {
                    v[2] = v[1]; ix[2] = ix[1];
                    if (better(q, qi, v[0], ix[0])) {
                        v[1] = v[0]; ix[1] = ix[0];
                        v[0] = q; ix[0] = qi;
                    } else { v[1] = q; ix[1] = qi; }
                } else { v[2] = q; ix[2] = qi; }
            } else { v[3] = q; ix[3] = qi; }
        }
    }
    const int p = ix[k];        // this thread's winner

    // Encode one output row.
    float gx1 = targets[(size_t)bg * 4 + 0];
    float gy1 = targets[(size_t)bg * 4 + 1];
    float gx2 = targets[(size_t)bg * 4 + 2];
    float gy2 = targets[(size_t)bg * 4 + 3];
    float gcx = (gx1 + gx2) * 0.5f;
    float gcy = (gy1 + gy2) * 0.5f;
    float gw  = gx2 - gx1;
    float gh  = gy2 - gy1;

    const float4* pri = (const float4*)(rois + ((size_t)b * 2 + 1) * (size_t)NP * 4);
    float4 pr = __ldg(&pri[p]);
    float pcx = (pr.x + pr.z) * 0.5f;
    float pcy = (pr.y + pr.w) * 0.5f;
    float pw  = pr.z - pr.x;
    float ph  = pr.w - pr.y;
    float4 o;
    o.x = (gcx - pcx) / (0.1f * pw);
    o.y = (gcy - pcy) / (0.1f * ph);
    o.z = logf(gw / pw) / 0.2f;
    o.w = logf(gh / ph) / 0.2f;
    ((float4*)out)[t] = o;
}

extern "C" void kernel_launch(void* const* d_in, const int* in_sizes, int n_in,
                              void* d_out, int out_size) {
    const float* rois    = (const float*)d_in[0];   // (16, 2, 32768, 4) f32
    const float* targets = (const float*)d_in[1];   // (16, 128, 4) f32
    float* out           = (float*)d_out;           // (16, 512, 4) f32
    (void)in_sizes; (void)n_in; (void)out_size;

    ptl_phase1<<<NB * (NG / WPB) * CSPLIT, NT1>>>(rois, targets);
    ptl_phase2<<<(NBG * TK) / 128, 128>>>(rois, targets, out);
}